// round 2
// baseline (speedup 1.0000x reference)
#include <cuda_runtime.h>

#define IC 1152
#define OC 10
#define ID 8
#define OD 16
#define BATCH 32
#define NITER 5
#define EPSV 1e-20f
#define ICPB 4
#define NTHREADS 320   // 10 warps: warp = oc, lane = b

__global__ void zero_out_kernel(float* out, int n) {
    int i = blockIdx.x * blockDim.x + threadIdx.x;
    if (i < n) out[i] = 0.0f;
}

__global__ __launch_bounds__(NTHREADS, 2)
void caps_kernel(const float* __restrict__ x,
                 const float* __restrict__ w,
                 float* __restrict__ out) {
    __shared__ float w_s[OC * ID * OD];       // 1280 floats, current ic slab
    __shared__ float x_s[BATCH][ID + 1];      // padded to kill bank conflicts
    __shared__ float alpha_s[BATCH][OC];

    const int tid = threadIdx.x;
    const int b   = tid & 31;     // lane
    const int oc  = tid >> 5;     // warp

    float res[OD];
#pragma unroll
    for (int od = 0; od < OD; od++) res[od] = 0.0f;

    for (int k = 0; k < ICPB; k++) {
        const int ic = blockIdx.x * ICPB + k;

        // ---- stage weights slab [OC][ID][OD] and x slab [B][ID] into smem ----
        for (int i = tid; i < OC * ID * OD; i += NTHREADS)
            w_s[i] = w[ic * (OC * ID * OD) + i];
        for (int i = tid; i < BATCH * ID; i += NTHREADS) {
            int bb = i >> 3, id = i & 7;
            x_s[bb][id] = x[(bb * IC + ic) * ID + id];
        }
        __syncthreads();

        // ---- normalize x over ID (per-thread copy in registers) ----
        float xn[ID];
        float xs = 0.0f;
#pragma unroll
        for (int id = 0; id < ID; id++) { xn[id] = x_s[b][id]; xs += xn[id]; }
        float xr = __fdividef(1.0f, xs + EPSV);
#pragma unroll
        for (int id = 0; id < ID; id++) xn[id] *= xr;

        const float* wp = &w_s[oc * ID * OD];

        // ---- NNMF successive substitution, 5 iterations ----
        float outv[OD];
#pragma unroll
        for (int od = 0; od < OD; od++) outv[od] = 1.0f / OD;

        for (int it = 0; it < NITER; it++) {
            float acc[OD];
#pragma unroll
            for (int od = 0; od < OD; od++) acc[od] = 0.0f;
#pragma unroll
            for (int id = 0; id < ID; id++) {
                float h[OD];
                float rs0 = 0.f, rs1 = 0.f, rs2 = 0.f, rs3 = 0.f;
#pragma unroll
                for (int od = 0; od < OD; od += 4) {
                    h[od + 0] = outv[od + 0] * wp[id * OD + od + 0];
                    h[od + 1] = outv[od + 1] * wp[id * OD + od + 1];
                    h[od + 2] = outv[od + 2] * wp[id * OD + od + 2];
                    h[od + 3] = outv[od + 3] * wp[id * OD + od + 3];
                    rs0 += h[od + 0]; rs1 += h[od + 1];
                    rs2 += h[od + 2]; rs3 += h[od + 3];
                }
                float rs = (rs0 + rs1) + (rs2 + rs3);
                float s = __fdividef(xn[id], rs + EPSV);
#pragma unroll
                for (int od = 0; od < OD; od++) acc[od] += h[od] * s;
            }
            float t0 = 0.f, t1 = 0.f, t2 = 0.f, t3 = 0.f;
#pragma unroll
            for (int od = 0; od < OD; od += 4) {
                t0 += acc[od]; t1 += acc[od + 1];
                t2 += acc[od + 2]; t3 += acc[od + 3];
            }
            float rn = __fdividef(1.0f, (t0 + t1) + (t2 + t3) + EPSV);
#pragma unroll
            for (int od = 0; od < OD; od++) outv[od] = acc[od] * rn;
        }

        // ---- reconstruct + alpha ----
        float alpha = 0.0f;
#pragma unroll
        for (int id = 0; id < ID; id++) {
            float rc0 = 0.f, rc1 = 0.f, rc2 = 0.f, rc3 = 0.f;
#pragma unroll
            for (int od = 0; od < OD; od += 4) {
                rc0 += outv[od + 0] * wp[id * OD + od + 0];
                rc1 += outv[od + 1] * wp[id * OD + od + 1];
                rc2 += outv[od + 2] * wp[id * OD + od + 2];
                rc3 += outv[od + 3] * wp[id * OD + od + 3];
            }
            alpha += ((rc0 + rc1) + (rc2 + rc3)) * xn[id];
        }

        alpha_s[b][oc] = alpha;
        __syncthreads();

        float asum = 0.0f;
#pragma unroll
        for (int o2 = 0; o2 < OC; o2++) asum += alpha_s[b][o2];
        float an = alpha * __fdividef(1.0f, asum + EPSV);

#pragma unroll
        for (int od = 0; od < OD; od++) res[od] += outv[od] * an;
        __syncthreads();   // protect smem before next-ic overwrite
    }

    // ---- accumulate over ic via global atomics (288 adds per address) ----
#pragma unroll
    for (int od = 0; od < OD; od++)
        atomicAdd(&out[(b * OC + oc) * OD + od], res[od]);
}

extern "C" void kernel_launch(void* const* d_in, const int* in_sizes, int n_in,
                              void* d_out, int out_size) {
    const float* x = (const float*)d_in[0];   // [32, 1152, 8]
    const float* w = (const float*)d_in[1];   // [1152, 10, 8, 16]
    float* out = (float*)d_out;               // [32, 10, 16]

    zero_out_kernel<<<(BATCH * OC * OD + 255) / 256, 256>>>(out, BATCH * OC * OD);
    caps_kernel<<<IC / ICPB, NTHREADS>>>(x, w, out);
}

// round 3
// speedup vs baseline: 1.0555x; 1.0555x over previous
#include <cuda_runtime.h>

#define IC 1152
#define OC 10
#define ID 8
#define OD 16
#define OD2 8          // packed f32x2 pairs
#define BATCH 32
#define NITER 5
#define EPSV 1e-20f
#define ICPB 4
#define NTHREADS 320   // 10 warps: warp = oc, lane = b
#define WSLAB (OC * ID * OD)   // 1280 floats per ic

typedef unsigned long long u64;

__device__ __forceinline__ u64 pk2(float lo, float hi) {
    u64 r; asm("mov.b64 %0, {%1,%2};" : "=l"(r) : "f"(lo), "f"(hi)); return r;
}
__device__ __forceinline__ float2 upk2(u64 v) {
    float2 f; asm("mov.b64 {%0,%1}, %2;" : "=f"(f.x), "=f"(f.y) : "l"(v)); return f;
}
__device__ __forceinline__ u64 mul2(u64 a, u64 b) {
    u64 r; asm("mul.rn.f32x2 %0, %1, %2;" : "=l"(r) : "l"(a), "l"(b)); return r;
}
__device__ __forceinline__ u64 add2(u64 a, u64 b) {
    u64 r; asm("add.rn.f32x2 %0, %1, %2;" : "=l"(r) : "l"(a), "l"(b)); return r;
}
__device__ __forceinline__ u64 fma2(u64 a, u64 b, u64 c) {
    u64 r; asm("fma.rn.f32x2 %0, %1, %2, %3;" : "=l"(r) : "l"(a), "l"(b), "l"(c)); return r;
}

__global__ void zero_out_kernel(float* out, int n) {
    int i = blockIdx.x * blockDim.x + threadIdx.x;
    if (i < n) out[i] = 0.0f;
}

__global__ __launch_bounds__(NTHREADS, 2)
void caps_kernel(const float* __restrict__ x,
                 const float* __restrict__ w,
                 float* __restrict__ out) {
    __shared__ __align__(16) float w_s[WSLAB];      // current ic weight slab
    __shared__ float x_s[BATCH][ID + 1];            // padded: stride 9 kills conflicts
    __shared__ float alpha_s[BATCH][OC];

    const int tid = threadIdx.x;
    const int b   = tid & 31;     // lane
    const int oc  = tid >> 5;     // warp

    u64 res2[OD2];
#pragma unroll
    for (int j = 0; j < OD2; j++) res2[j] = 0ull;

    // ---- load slab 0 ----
    {
        const int ic0 = blockIdx.x * ICPB;
        for (int i = tid; i < WSLAB; i += NTHREADS)
            w_s[i] = w[ic0 * WSLAB + i];
        if (tid < BATCH * ID) {
            int bb = tid >> 3, id = tid & 7;
            x_s[bb][id] = x[(bb * IC + ic0) * ID + id];
        }
    }
    __syncthreads();

    for (int k = 0; k < ICPB; k++) {
        const int ic = blockIdx.x * ICPB + k;

        // ---- prefetch next slab into registers (hidden behind compute) ----
        float wpre0 = 0.f, wpre1 = 0.f, wpre2 = 0.f, wpre3 = 0.f, xpre = 0.f;
        if (k + 1 < ICPB) {
            const float* wn = w + (ic + 1) * WSLAB;
            wpre0 = wn[tid];
            wpre1 = wn[tid + NTHREADS];
            wpre2 = wn[tid + 2 * NTHREADS];
            wpre3 = wn[tid + 3 * NTHREADS];
            if (tid < BATCH * ID)
                xpre = x[((tid >> 3) * IC + ic + 1) * ID + (tid & 7)];
        }

        // ---- normalize x over ID ----
        float xn[ID];
        float xs = 0.0f;
#pragma unroll
        for (int id = 0; id < ID; id++) { xn[id] = x_s[b][id]; xs += xn[id]; }
        float xr = __fdividef(1.0f, xs + EPSV);
#pragma unroll
        for (int id = 0; id < ID; id++) xn[id] *= xr;

        const u64* wq = reinterpret_cast<const u64*>(w_s + oc * ID * OD);

        // ---- NNMF: per-iteration out-normalization dropped (scale-invariant);
        //      only the final iteration normalizes ----
        u64 outv2[OD2];
#pragma unroll
        for (int j = 0; j < OD2; j++) outv2[j] = pk2(1.0f / OD, 1.0f / OD);

#pragma unroll
        for (int it = 0; it < NITER; it++) {
            u64 acc2[OD2];
#pragma unroll
            for (int j = 0; j < OD2; j++) acc2[j] = 0ull;
#pragma unroll
            for (int id = 0; id < ID; id++) {
                u64 h[OD2];
#pragma unroll
                for (int j = 0; j < OD2; j++)
                    h[j] = mul2(outv2[j], wq[id * OD2 + j]);
                u64 s01 = add2(h[0], h[1]), s23 = add2(h[2], h[3]);
                u64 s45 = add2(h[4], h[5]), s67 = add2(h[6], h[7]);
                u64 st  = add2(add2(s01, s23), add2(s45, s67));
                float2 sf = upk2(st);
                float s = __fdividef(xn[id], sf.x + sf.y + EPSV);
                u64 s2 = pk2(s, s);
#pragma unroll
                for (int j = 0; j < OD2; j++)
                    acc2[j] = fma2(h[j], s2, acc2[j]);
            }
            if (it == NITER - 1) {
                u64 t01 = add2(acc2[0], acc2[1]), t23 = add2(acc2[2], acc2[3]);
                u64 t45 = add2(acc2[4], acc2[5]), t67 = add2(acc2[6], acc2[7]);
                u64 tt  = add2(add2(t01, t23), add2(t45, t67));
                float2 tf = upk2(tt);
                float rn = __fdividef(1.0f, tf.x + tf.y + EPSV);
                u64 rn2 = pk2(rn, rn);
#pragma unroll
                for (int j = 0; j < OD2; j++) outv2[j] = mul2(acc2[j], rn2);
            } else {
#pragma unroll
                for (int j = 0; j < OD2; j++) outv2[j] = acc2[j];
            }
        }

        // ---- reconstruct + alpha ----
        float alpha = 0.0f;
#pragma unroll
        for (int id = 0; id < ID; id++) {
            u64 a0 = mul2(outv2[0], wq[id * OD2 + 0]);
            u64 a1 = mul2(outv2[1], wq[id * OD2 + 1]);
            a0 = fma2(outv2[2], wq[id * OD2 + 2], a0);
            a1 = fma2(outv2[3], wq[id * OD2 + 3], a1);
            a0 = fma2(outv2[4], wq[id * OD2 + 4], a0);
            a1 = fma2(outv2[5], wq[id * OD2 + 5], a1);
            a0 = fma2(outv2[6], wq[id * OD2 + 6], a0);
            a1 = fma2(outv2[7], wq[id * OD2 + 7], a1);
            float2 rf = upk2(add2(a0, a1));
            alpha = fmaf(rf.x + rf.y, xn[id], alpha);
        }

        alpha_s[b][oc] = alpha;
        __syncthreads();   // all threads done reading w_s/x_s and writing alpha

        // ---- store prefetched slab (w_s/x_s no longer read this k) ----
        if (k + 1 < ICPB) {
            w_s[tid]                = wpre0;
            w_s[tid + NTHREADS]     = wpre1;
            w_s[tid + 2 * NTHREADS] = wpre2;
            w_s[tid + 3 * NTHREADS] = wpre3;
            if (tid < BATCH * ID)
                x_s[tid >> 3][tid & 7] = xpre;
        }

        float asum = 0.0f;
#pragma unroll
        for (int o2 = 0; o2 < OC; o2++) asum += alpha_s[b][o2];
        float an = alpha * __fdividef(1.0f, asum + EPSV);
        u64 an2 = pk2(an, an);
#pragma unroll
        for (int j = 0; j < OD2; j++)
            res2[j] = fma2(outv2[j], an2, res2[j]);

        __syncthreads();   // new slab visible + alpha_s reads complete
    }

    // ---- accumulate over ic (288 blocks per address — cheap) ----
#pragma unroll
    for (int j = 0; j < OD2; j++) {
        float2 f = upk2(res2[j]);
        atomicAdd(&out[(b * OC + oc) * OD + 2 * j],     f.x);
        atomicAdd(&out[(b * OC + oc) * OD + 2 * j + 1], f.y);
    }
}

extern "C" void kernel_launch(void* const* d_in, const int* in_sizes, int n_in,
                              void* d_out, int out_size) {
    const float* x = (const float*)d_in[0];   // [32, 1152, 8]
    const float* w = (const float*)d_in[1];   // [1152, 10, 8, 16]
    float* out = (float*)d_out;               // [32, 10, 16]

    zero_out_kernel<<<(BATCH * OC * OD + 255) / 256, 256>>>(out, BATCH * OC * OD);
    caps_kernel<<<IC / ICPB, NTHREADS>>>(x, w, out);
}